// round 4
// baseline (speedup 1.0000x reference)
#include <cuda_runtime.h>

#define B_    4096
#define NNODE 64
#define FIN   67
#define C1    64
#define C2    32
#define DFP   2048
#define H1D   400
#define H2D   64
#define NEDGE 512

// ---------------- scratch (device globals; no allocations allowed) ----------------
__device__ float g_P [NNODE * NNODE];            // propagation matrix P[d][s]
__device__ float g_Y1[B_ * NNODE * C1];          // X @ W1^T
__device__ float g_G1[B_ * NNODE * C1];          // P @ Y1 + b1 (pre-BN)
__device__ float g_Z2[B_ * NNODE * C2];          // relu(bn(G1)) @ W2^T
__device__ float g_G2[B_ * NNODE * C2];          // P @ Z2 + b2 (pre-BN)
__device__ float g_pool[B_ * C2];
__device__ float g_H1[B_ * H1D];
__device__ float g_H2[B_ * H2D];
__device__ float g_sum1[NNODE], g_ssq1[NNODE], g_sum2[NNODE], g_ssq2[NNODE];
__device__ float g_a1[NNODE], g_c1[NNODE], g_a2[NNODE], g_c2[NNODE];

// ---------------- K0: build P from edge list, zero stats ----------------
__global__ void k_prep(const int* __restrict__ el) {
    __shared__ float deg[NNODE];
    __shared__ float dinv[NNODE];
    __shared__ float Ps[NNODE * NNODE];
    int t = threadIdx.x;
    if (t < NNODE) deg[t] = 0.f;
    for (int i = t; i < NNODE * NNODE; i += 256) Ps[i] = 0.f;
    __syncthreads();
    for (int i = t; i < NEDGE + NNODE; i += 256) {
        int d = (i < NEDGE) ? el[NEDGE + i] : (i - NEDGE);
        atomicAdd(&deg[d], 1.f);
    }
    __syncthreads();
    if (t < NNODE) dinv[t] = (deg[t] > 0.f) ? rsqrtf(deg[t]) : 0.f;
    __syncthreads();
    for (int i = t; i < NEDGE + NNODE; i += 256) {
        int s = (i < NEDGE) ? el[i] : (i - NEDGE);
        int d = (i < NEDGE) ? el[NEDGE + i] : (i - NEDGE);
        atomicAdd(&Ps[d * NNODE + s], dinv[s] * dinv[d]);
    }
    __syncthreads();
    for (int i = t; i < NNODE * NNODE; i += 256) g_P[i] = Ps[i];
    if (t < NNODE) { g_sum1[t] = 0.f; g_ssq1[t] = 0.f; g_sum2[t] = 0.f; g_ssq2[t] = 0.f; }
}

// ---------------- K1: Y1 = X @ W1^T  (M=262144, K=67, N=64) ----------------
__global__ void k_gemm1(const float* __restrict__ X, const float* __restrict__ W1) {
    __shared__ __align__(16) float As[FIN * 68];   // As[k][m], m padded to 68
    __shared__ __align__(16) float Ws[FIN * 68];   // Ws[k][n]
    int t = threadIdx.x;
    int m0 = blockIdx.x * 64;
    const float* Xt = X + (size_t)m0 * FIN;
    for (int i = t; i < 64 * FIN; i += 256) {
        int r = i / FIN, k = i - r * FIN;
        As[k * 68 + r] = Xt[i];
    }
    for (int i = t; i < 64 * FIN; i += 256) {
        int n = i / FIN, k = i - n * FIN;
        Ws[k * 68 + n] = W1[i];
    }
    __syncthreads();
    int tm = (t >> 4) * 4, tn = (t & 15) * 4;
    float acc[4][4] = {};
    for (int k = 0; k < FIN; k++) {
        float4 a = *reinterpret_cast<const float4*>(&As[k * 68 + tm]);
        float4 b = *reinterpret_cast<const float4*>(&Ws[k * 68 + tn]);
        acc[0][0] = fmaf(a.x, b.x, acc[0][0]); acc[0][1] = fmaf(a.x, b.y, acc[0][1]);
        acc[0][2] = fmaf(a.x, b.z, acc[0][2]); acc[0][3] = fmaf(a.x, b.w, acc[0][3]);
        acc[1][0] = fmaf(a.y, b.x, acc[1][0]); acc[1][1] = fmaf(a.y, b.y, acc[1][1]);
        acc[1][2] = fmaf(a.y, b.z, acc[1][2]); acc[1][3] = fmaf(a.y, b.w, acc[1][3]);
        acc[2][0] = fmaf(a.z, b.x, acc[2][0]); acc[2][1] = fmaf(a.z, b.y, acc[2][1]);
        acc[2][2] = fmaf(a.z, b.z, acc[2][2]); acc[2][3] = fmaf(a.z, b.w, acc[2][3]);
        acc[3][0] = fmaf(a.w, b.x, acc[3][0]); acc[3][1] = fmaf(a.w, b.y, acc[3][1]);
        acc[3][2] = fmaf(a.w, b.z, acc[3][2]); acc[3][3] = fmaf(a.w, b.w, acc[3][3]);
    }
    #pragma unroll
    for (int i = 0; i < 4; i++) {
        float4 v = make_float4(acc[i][0], acc[i][1], acc[i][2], acc[i][3]);
        *reinterpret_cast<float4*>(&g_Y1[(size_t)(m0 + tm + i) * 64 + tn]) = v;
    }
}

// ---------------- K2: G1[b] = P @ Y1[b] + b1 ----------------
__global__ void k_pgemm1(const float* __restrict__ b1) {
    __shared__ __align__(16) float Ps[4096];
    __shared__ __align__(16) float Ys[4096];
    int b = blockIdx.x, t = threadIdx.x;
    const float* src = g_Y1 + (size_t)b * 4096;
    for (int i = t; i < 4096; i += 256) { Ps[i] = g_P[i]; Ys[i] = src[i]; }
    __syncthreads();
    int d0 = (t >> 4) * 4, o0 = (t & 15) * 4;
    float acc[4][4] = {};
    #pragma unroll 4
    for (int s = 0; s < 64; s++) {
        float4 y = *reinterpret_cast<const float4*>(&Ys[s * 64 + o0]);
        #pragma unroll
        for (int i = 0; i < 4; i++) {
            float p = Ps[(d0 + i) * 64 + s];
            acc[i][0] = fmaf(p, y.x, acc[i][0]);
            acc[i][1] = fmaf(p, y.y, acc[i][1]);
            acc[i][2] = fmaf(p, y.z, acc[i][2]);
            acc[i][3] = fmaf(p, y.w, acc[i][3]);
        }
    }
    float4 bb = *reinterpret_cast<const float4*>(&b1[o0]);
    float* out = g_G1 + (size_t)b * 4096;
    #pragma unroll
    for (int i = 0; i < 4; i++) {
        float4 v = make_float4(acc[i][0] + bb.x, acc[i][1] + bb.y,
                               acc[i][2] + bb.z, acc[i][3] + bb.w);
        *reinterpret_cast<float4*>(&out[(d0 + i) * 64 + o0]) = v;
    }
}

// ---------------- per-node BN statistics (sum / sumsq over B and C) ----------------
template <int C>
__device__ __forceinline__ void stats_body(const float* __restrict__ G,
                                           float* __restrict__ sumO,
                                           float* __restrict__ ssqO) {
    int d = blockIdx.y;
    int chunk = blockIdx.x;            // 8 chunks of 512 batch elems
    int t = threadIdx.x;
    int o = t & (C - 1);
    int bl = t / C;
    const int RP = 256 / C;
    float s = 0.f, q = 0.f;
    int bend = (chunk + 1) * 512;
    for (int b = chunk * 512 + bl; b < bend; b += RP) {
        float v = G[((size_t)b * NNODE + d) * C + o];
        s += v; q = fmaf(v, v, q);
    }
    __shared__ float r1[256], r2[256];
    r1[t] = s; r2[t] = q;
    __syncthreads();
    for (int st = 128; st > 0; st >>= 1) {
        if (t < st) { r1[t] += r1[t + st]; r2[t] += r2[t + st]; }
        __syncthreads();
    }
    if (t == 0) { atomicAdd(&sumO[d], r1[0]); atomicAdd(&ssqO[d], r2[0]); }
}
__global__ void k_stats1() { stats_body<C1>(g_G1, g_sum1, g_ssq1); }
__global__ void k_stats2() { stats_body<C2>(g_G2, g_sum2, g_ssq2); }

// ---------------- finalize BN scale/shift ----------------
__global__ void k_bnfin(int stage, const float* __restrict__ gamma,
                        const float* __restrict__ beta, float invn) {
    int t = threadIdx.x;
    if (t < NNODE) {
        const float* sum = stage ? g_sum2 : g_sum1;
        const float* ssq = stage ? g_ssq2 : g_ssq1;
        float* a = stage ? g_a2 : g_a1;
        float* c = stage ? g_c2 : g_c1;
        float m = sum[t] * invn;
        float v = ssq[t] * invn - m * m;
        float r = rsqrtf(v + 1e-5f);
        float aa = gamma[t] * r;
        a[t] = aa;
        c[t] = beta[t] - m * aa;
    }
}

// ---------------- K3: Z2[b] = relu(bn(G1[b])) @ W2^T ----------------
__global__ void k_gemm2(const float* __restrict__ W2) {
    __shared__ float a1s[64], c1s[64];
    __shared__ __align__(16) float G1s[4096];
    __shared__ __align__(16) float W2t[64 * 36];   // W2t[o][j], j padded to 36
    int b = blockIdx.x, t = threadIdx.x;
    if (t < 64) { a1s[t] = g_a1[t]; c1s[t] = g_c1[t]; }
    __syncthreads();
    const float* src = g_G1 + (size_t)b * 4096;
    for (int i = t; i < 4096; i += 256) {
        int d = i >> 6;
        G1s[i] = fmaxf(fmaf(src[i], a1s[d], c1s[d]), 0.f);
    }
    for (int i = t; i < 2048; i += 256) {
        int j = i >> 6, o = i & 63;
        W2t[o * 36 + j] = W2[i];
    }
    __syncthreads();
    int d0 = (t >> 3) * 2, j0 = (t & 7) * 4;
    float acc[2][4] = {};
    #pragma unroll 4
    for (int o = 0; o < 64; o++) {
        float4 w = *reinterpret_cast<const float4*>(&W2t[o * 36 + j0]);
        float gA = G1s[d0 * 64 + o];
        float gB = G1s[d0 * 64 + 64 + o];
        acc[0][0] = fmaf(gA, w.x, acc[0][0]); acc[0][1] = fmaf(gA, w.y, acc[0][1]);
        acc[0][2] = fmaf(gA, w.z, acc[0][2]); acc[0][3] = fmaf(gA, w.w, acc[0][3]);
        acc[1][0] = fmaf(gB, w.x, acc[1][0]); acc[1][1] = fmaf(gB, w.y, acc[1][1]);
        acc[1][2] = fmaf(gB, w.z, acc[1][2]); acc[1][3] = fmaf(gB, w.w, acc[1][3]);
    }
    float* out = g_Z2 + (size_t)b * 2048;
    *reinterpret_cast<float4*>(&out[d0 * 32 + j0]) =
        make_float4(acc[0][0], acc[0][1], acc[0][2], acc[0][3]);
    *reinterpret_cast<float4*>(&out[(d0 + 1) * 32 + j0]) =
        make_float4(acc[1][0], acc[1][1], acc[1][2], acc[1][3]);
}

// ---------------- K4: G2[b] = P @ Z2[b] + b2 ----------------
__global__ void k_pgemm2(const float* __restrict__ b2) {
    __shared__ __align__(16) float Ps[4096];
    __shared__ __align__(16) float Zs[2048];
    int b = blockIdx.x, t = threadIdx.x;
    const float* src = g_Z2 + (size_t)b * 2048;
    for (int i = t; i < 4096; i += 256) Ps[i] = g_P[i];
    for (int i = t; i < 2048; i += 256) Zs[i] = src[i];
    __syncthreads();
    int d0 = (t >> 4) * 4, j0 = (t & 15) * 2;
    float acc[4][2] = {};
    #pragma unroll 4
    for (int s = 0; s < 64; s++) {
        float2 z = *reinterpret_cast<const float2*>(&Zs[s * 32 + j0]);
        #pragma unroll
        for (int i = 0; i < 4; i++) {
            float p = Ps[(d0 + i) * 64 + s];
            acc[i][0] = fmaf(p, z.x, acc[i][0]);
            acc[i][1] = fmaf(p, z.y, acc[i][1]);
        }
    }
    float2 bb = *reinterpret_cast<const float2*>(&b2[j0]);
    float* out = g_G2 + (size_t)b * 2048;
    #pragma unroll
    for (int i = 0; i < 4; i++) {
        *reinterpret_cast<float2*>(&out[(d0 + i) * 32 + j0]) =
            make_float2(acc[i][0] + bb.x, acc[i][1] + bb.y);
    }
}

// ---------------- K5: bn + relu + max-pool over nodes ----------------
__global__ void k_pool() {
    __shared__ float a2s[64], c2s[64];
    int t = threadIdx.x;
    if (t < 64) { a2s[t] = g_a2[t]; c2s[t] = g_c2[t]; }
    __syncthreads();
    int bl = t >> 5, j = t & 31;
    int b = blockIdx.x * 8 + bl;
    const float* src = g_G2 + (size_t)b * 2048 + j;
    float m = 0.f;   // relu outputs are >= 0, so 0 is a valid identity
    #pragma unroll 8
    for (int d = 0; d < 64; d++) {
        float v = fmaxf(fmaf(src[d * 32], a2s[d], c2s[d]), 0.f);
        m = fmaxf(m, v);
    }
    g_pool[b * 32 + j] = m;
}

// ---------------- MLP GEMM: C = relu(A @ B^T + bias) ----------------
// MODE 0: A = Ain (fingerprints), C = g_H1.   MODE 1: A = g_H1, C = g_H2.
template <int MODE, bool GN>
__global__ void k_mlp(const float* __restrict__ Ain, const float* __restrict__ Bw,
                      const float* __restrict__ bias, int Ncols, int K) {
    __shared__ __align__(16) float As[16 * 68];
    __shared__ __align__(16) float Bs[16 * 68];
    const float* A = (MODE == 0) ? Ain : g_H1;
    float* C = (MODE == 0) ? g_H1 : g_H2;
    int m0 = blockIdx.x * 64, n0 = blockIdx.y * 64;
    int t = threadIdx.x;
    int tm = (t >> 4) * 4, tn = (t & 15) * 4;
    float acc[4][4] = {};
    for (int k0 = 0; k0 < K; k0 += 16) {
        for (int i = t; i < 1024; i += 256) {
            int r = i >> 4, kk = i & 15;
            As[kk * 68 + r] = A[(size_t)(m0 + r) * K + k0 + kk];
            float bv = 0.f;
            if (!GN || (n0 + r) < Ncols) bv = Bw[(size_t)(n0 + r) * K + k0 + kk];
            Bs[kk * 68 + r] = bv;
        }
        __syncthreads();
        #pragma unroll
        for (int kk = 0; kk < 16; kk++) {
            float4 a = *reinterpret_cast<const float4*>(&As[kk * 68 + tm]);
            float4 b = *reinterpret_cast<const float4*>(&Bs[kk * 68 + tn]);
            acc[0][0] = fmaf(a.x, b.x, acc[0][0]); acc[0][1] = fmaf(a.x, b.y, acc[0][1]);
            acc[0][2] = fmaf(a.x, b.z, acc[0][2]); acc[0][3] = fmaf(a.x, b.w, acc[0][3]);
            acc[1][0] = fmaf(a.y, b.x, acc[1][0]); acc[1][1] = fmaf(a.y, b.y, acc[1][1]);
            acc[1][2] = fmaf(a.y, b.z, acc[1][2]); acc[1][3] = fmaf(a.y, b.w, acc[1][3]);
            acc[2][0] = fmaf(a.z, b.x, acc[2][0]); acc[2][1] = fmaf(a.z, b.y, acc[2][1]);
            acc[2][2] = fmaf(a.z, b.z, acc[2][2]); acc[2][3] = fmaf(a.z, b.w, acc[2][3]);
            acc[3][0] = fmaf(a.w, b.x, acc[3][0]); acc[3][1] = fmaf(a.w, b.y, acc[3][1]);
            acc[3][2] = fmaf(a.w, b.z, acc[3][2]); acc[3][3] = fmaf(a.w, b.w, acc[3][3]);
        }
        __syncthreads();
    }
    #pragma unroll
    for (int i = 0; i < 4; i++) {
        int row = m0 + tm + i;
        #pragma unroll
        for (int j = 0; j < 4; j++) {
            int col = n0 + tn + j;
            if (!GN || col < Ncols) {
                C[(size_t)row * Ncols + col] = fmaxf(acc[i][j] + __ldg(&bias[col]), 0.f);
            }
        }
    }
}

// ---------------- final: out = [pool, H2] @ Wfc^T + bfc ----------------
__global__ void k_final(const float* __restrict__ Wfc, const float* __restrict__ bfc,
                        float* __restrict__ out) {
    __shared__ float Ws[192];
    int t = threadIdx.x;
    if (t < 192) Ws[t] = Wfc[t];
    __syncthreads();
    int b = blockIdx.x * 256 + t;
    float a0 = __ldg(&bfc[0]), a1 = __ldg(&bfc[1]);
    const float* pp = g_pool + b * 32;
    const float* hh = g_H2 + b * 64;
    #pragma unroll
    for (int j = 0; j < 32; j++) {
        float v = pp[j];
        a0 = fmaf(v, Ws[j], a0);
        a1 = fmaf(v, Ws[96 + j], a1);
    }
    #pragma unroll
    for (int j = 0; j < 64; j++) {
        float v = hh[j];
        a0 = fmaf(v, Ws[32 + j], a0);
        a1 = fmaf(v, Ws[128 + j], a1);
    }
    out[b * 2]     = a0;
    out[b * 2 + 1] = a1;
}

// ---------------- launch ----------------
extern "C" void kernel_launch(void* const* d_in, const int* in_sizes, int n_in,
                              void* d_out, int out_size) {
    const float* xf  = (const float*)d_in[0];
    const float* xn  = (const float*)d_in[1];
    const int*   el  = (const int*)  d_in[2];
    const float* W1  = (const float*)d_in[3];
    const float* b1  = (const float*)d_in[4];
    const float* g1  = (const float*)d_in[5];
    const float* be1 = (const float*)d_in[6];
    const float* W2  = (const float*)d_in[7];
    const float* b2  = (const float*)d_in[8];
    const float* g2  = (const float*)d_in[9];
    const float* be2 = (const float*)d_in[10];
    const float* Wl1 = (const float*)d_in[11];
    const float* bl1 = (const float*)d_in[12];
    const float* Wl2 = (const float*)d_in[13];
    const float* bl2 = (const float*)d_in[14];
    const float* Wfc = (const float*)d_in[15];
    const float* bfc = (const float*)d_in[16];
    float* out = (float*)d_out;

    k_prep<<<1, 256>>>(el);

    // graph path
    k_gemm1<<<(B_ * NNODE) / 64, 256>>>(xn, W1);
    k_pgemm1<<<B_, 256>>>(b1);
    k_stats1<<<dim3(8, NNODE), 256>>>();
    k_bnfin<<<1, 64>>>(0, g1, be1, 1.0f / (float)(B_ * C1));
    k_gemm2<<<B_, 256>>>(W2);
    k_pgemm2<<<B_, 256>>>(b2);
    k_stats2<<<dim3(8, NNODE), 256>>>();
    k_bnfin<<<1, 64>>>(1, g2, be2, 1.0f / (float)(B_ * C2));
    k_pool<<<B_ / 8, 256>>>();

    // fingerprint MLP path
    k_mlp<0, true ><<<dim3(B_ / 64, 7), 256>>>(xf, Wl1, bl1, H1D, DFP);
    k_mlp<1, false><<<dim3(B_ / 64, 1), 256>>>(nullptr, Wl2, bl2, H2D, H1D);

    k_final<<<B_ / 256, 256>>>(Wfc, bfc, out);
}